// round 3
// baseline (speedup 1.0000x reference)
#include <cuda_runtime.h>
#include <cuda_bf16.h>
#include <math.h>
#include <stdint.h>
#include <stddef.h>

#define NN 65536
#define EE 1048576
#define FMAXV 3.402823466e38f

typedef unsigned long long u64;

__device__ __forceinline__ void fma2(u64& d, u64 a, u64 b) {
    asm("fma.rn.f32x2 %0, %1, %2, %3;" : "=l"(d) : "l"(a), "l"(b), "l"(d));
}
__device__ __forceinline__ float f2lo(u64 v) { return __uint_as_float((unsigned)v); }
__device__ __forceinline__ float f2hi(u64 v) { return __uint_as_float((unsigned)(v >> 32)); }

// ---------------- static device scratch (no allocations) ----------------
__device__ float g_e[(size_t)EE * 32];      // edge_attr @ W_edge^T (no bias)
__device__ float g_c[(size_t)EE * 128];     // e @ Wpre_edgepart
__device__ float g_a[(size_t)NN * 128];     // dst-side node pre-part
__device__ float g_b[(size_t)NN * 128];     // src-side node pre-part
__device__ float g_agg[(size_t)NN * 512];   // per node/tower: [mean|mx|mn|std] x32
__device__ float g_Z[(size_t)NN * 128];     // post-MLP output
__device__ float g_s1[NN];
__device__ float g_s2[NN];
__device__ int   g_cnt[NN];
__device__ int   g_fill[NN];
__device__ int   g_rowptr[NN + 1];
__device__ int   g_eid[EE];
__device__ int   g_bsum[256];
__device__ float g_biasm[128];
__device__ float g_WedgeT[128 * 32];        // [k][f]
__device__ float g_WlinT[128 * 128];        // [k][c]
__device__ float g_avglog;

// ---------------- setup ----------------
__global__ void k_zero(void) {
    int i = blockIdx.x * 256 + threadIdx.x;
    if (i < NN) { g_cnt[i] = 0; g_fill[i] = 0; }
}

__global__ void k_prep(const float* __restrict__ W_edge, const float* __restrict__ W_lin,
                       const float* __restrict__ W_pre, const float* __restrict__ b_pre,
                       const float* __restrict__ b_edge) {
    int i = blockIdx.x * 256 + threadIdx.x;
    if (i < 128 * 32) {                      // WedgeT[k*32+f] = W_edge[f*128+k]
        int k = i >> 5, f = i & 31;
        g_WedgeT[i] = W_edge[f * 128 + k];
    }
    if (i < 128 * 128) {                     // WlinT[k*128+c] = W_lin[c*128+k]
        int k = i >> 7, c = i & 127;
        g_WlinT[i] = W_lin[c * 128 + k];
    }
    if (i < 128) {                           // biasm = b_pre + Wpre_e^T b_edge
        int t = i >> 5, g = i & 31;
        float s = b_pre[i];
        for (int j = 0; j < 32; j++)
            s += b_edge[j] * W_pre[t * 3072 + (64 + j) * 32 + g];
        g_biasm[i] = s;
    }
    if (i == 0) {                            // AVG_LOG in double, as reference
        const double cnts[6] = {108477.0, 299931.0, 180702.0, 10767.0, 3.0, 2.0};
        double num = 0.0, den = 0.0;
        for (int d = 0; d < 6; d++) { num += cnts[d] * log((double)(d + 1) + 1.0); den += cnts[d]; }
        g_avglog = (float)(num / den);
    }
}

// ---------------- CSR build ----------------
__global__ void k_hist(const int* __restrict__ dst) {
    int i = blockIdx.x * 256 + threadIdx.x;
    if (i < EE) atomicAdd(&g_cnt[dst[i]], 1);
}

// parallel scan: 256 blocks x 256 threads, block-exclusive + block sums
__global__ void k_scan1(void) {
    int b = blockIdx.x, t = threadIdx.x;
    int gi = b * 256 + t;
    int v = g_cnt[gi];
    int lane = t & 31, w = t >> 5;
    int incl = v;
#pragma unroll
    for (int off = 1; off < 32; off <<= 1) {
        int u = __shfl_up_sync(0xffffffffu, incl, off);
        if (lane >= off) incl += u;
    }
    __shared__ int wtot[8];
    __shared__ int woff[8];
    if (lane == 31) wtot[w] = incl;
    __syncthreads();
    if (t == 0) {
        int run = 0;
        for (int i = 0; i < 8; i++) { woff[i] = run; run += wtot[i]; }
        g_bsum[b] = run;
    }
    __syncthreads();
    g_rowptr[gi] = woff[w] + incl - v;
}

__global__ void k_scan2(void) {          // 1 block x 256: scan block sums (exclusive, in place)
    int t = threadIdx.x;
    int v = g_bsum[t];
    int lane = t & 31, w = t >> 5;
    int incl = v;
#pragma unroll
    for (int off = 1; off < 32; off <<= 1) {
        int u = __shfl_up_sync(0xffffffffu, incl, off);
        if (lane >= off) incl += u;
    }
    __shared__ int wtot[8];
    __shared__ int woff[8];
    if (lane == 31) wtot[w] = incl;
    __syncthreads();
    if (t == 0) {
        int run = 0;
        for (int i = 0; i < 8; i++) { woff[i] = run; run += wtot[i]; }
    }
    __syncthreads();
    g_bsum[t] = woff[w] + incl - v;
    if (t == 0) g_rowptr[NN] = EE;
}

__global__ void k_scan3(void) {          // add block offsets
    int b = blockIdx.x, t = threadIdx.x;
    g_rowptr[b * 256 + t] += g_bsum[b];
}

__global__ void k_scatter(const int* __restrict__ dst) {
    int i = blockIdx.x * 256 + threadIdx.x;
    if (i < EE) {
        int d = dst[i];
        int slot = g_rowptr[d] + atomicAdd(&g_fill[d], 1);
        g_eid[slot] = i;
    }
}

// ---------------- node pre-parts: a (dst rows of W_pre), b (src rows) ----------------
__global__ void k_ab(const float* __restrict__ x, const float* __restrict__ W_pre) {
    int i = blockIdx.x * 256 + threadIdx.x;
    if (i >= NN * 128) return;
    int n = i >> 7, ch = i & 127;
    int t = ch >> 5, g = ch & 31;
    const float* xr = x + (size_t)n * 128 + t * 32;
    const float* wa = W_pre + t * 3072 + g;        // rows 0..31
    const float* wb = wa + 1024;                   // rows 32..63
    float a = 0.f, b = 0.f;
#pragma unroll
    for (int f = 0; f < 32; f++) {
        float xv = __ldg(&xr[f]);
        a = fmaf(xv, __ldg(&wa[f * 32]), a);
        b = fmaf(xv, __ldg(&wb[f * 32]), b);
    }
    g_a[i] = a; g_b[i] = b;
}

// ---------------- e-GEMM: e[E,32] = edge_attr[E,128] @ WedgeT (f32x2) ----------------
__global__ __launch_bounds__(256) void k_egemm(const float* __restrict__ ea) {
    __shared__ float sA[128 * 66];   // duplicated pairs, stride 66 (bank-safe)
    __shared__ float sW[32 * 36];
    int r0b = blockIdx.x * 128;
    int tid = threadIdx.x;
    int c4 = (tid & 7) * 4;
    int rg = tid >> 3;               // 0..31, 4 rows each
    u64 acc[4][2];
#pragma unroll
    for (int r = 0; r < 4; r++) { acc[r][0] = 0ull; acc[r][1] = 0ull; }

    for (int k0 = 0; k0 < 128; k0 += 32) {
        __syncthreads();
        for (int i = tid; i < 128 * 8; i += 256) {
            int r = i >> 3, kg = (i & 7) * 4;
            float4 v = *(const float4*)&ea[(size_t)(r0b + r) * 128 + k0 + kg];
            float* p = &sA[r * 66 + kg * 2];
            *(float2*)(p + 0) = make_float2(v.x, v.x);
            *(float2*)(p + 2) = make_float2(v.y, v.y);
            *(float2*)(p + 4) = make_float2(v.z, v.z);
            *(float2*)(p + 6) = make_float2(v.w, v.w);
        }
        for (int i = tid; i < 32 * 8; i += 256) {
            int kk = i >> 3, fg = (i & 7) * 4;
            *(float4*)&sW[kk * 36 + fg] = *(const float4*)&g_WedgeT[(k0 + kk) * 32 + fg];
        }
        __syncthreads();
#pragma unroll
        for (int k = 0; k < 32; k++) {
            u64 w0 = *(u64*)&sW[k * 36 + c4];
            u64 w1 = *(u64*)&sW[k * 36 + c4 + 2];
#pragma unroll
            for (int r = 0; r < 4; r++) {
                u64 ap = *(u64*)&sA[(rg * 4 + r) * 66 + k * 2];
                fma2(acc[r][0], ap, w0);
                fma2(acc[r][1], ap, w1);
            }
        }
    }
#pragma unroll
    for (int r = 0; r < 4; r++) {
        int row = r0b + rg * 4 + r;
        *(u64*)&g_e[(size_t)row * 32 + c4]     = acc[r][0];
        *(u64*)&g_e[(size_t)row * 32 + c4 + 2] = acc[r][1];
    }
}

// ---------------- c-GEMM: c[E,128] = e[E,32] @ Wpre_edgepart (f32x2) ----------------
__global__ __launch_bounds__(256) void k_cgemm(const float* __restrict__ W_pre) {
    __shared__ float sA[64 * 64];    // duplicated pairs, stride 64 (broadcast reads)
    __shared__ float sW[32 * 128];   // [j][o], o = t*32+g
    int r0b = blockIdx.x * 64;
    int tid = threadIdx.x;
    for (int i = tid; i < 32 * 32; i += 256) {
        int j = i >> 5, og = (i & 31) * 4;
        int t = og >> 5, g = og & 31;
        *(float4*)&sW[j * 128 + og] = *(const float4*)&W_pre[t * 3072 + (64 + j) * 32 + g];
    }
    for (int i = tid; i < 64 * 8; i += 256) {
        int r = i >> 3, kg = (i & 7) * 4;
        float4 v = *(const float4*)&g_e[(size_t)(r0b + r) * 32 + kg];
        *(float4*)&sA[r * 64 + kg * 2]     = make_float4(v.x, v.x, v.y, v.y);
        *(float4*)&sA[r * 64 + kg * 2 + 4] = make_float4(v.z, v.z, v.w, v.w);
    }
    __syncthreads();
    int c4 = (tid & 31) * 4;
    int rg = tid >> 5;
    u64 acc[8][2];
#pragma unroll
    for (int r = 0; r < 8; r++) { acc[r][0] = 0ull; acc[r][1] = 0ull; }
#pragma unroll
    for (int k = 0; k < 32; k++) {
        u64 w0 = *(u64*)&sW[k * 128 + c4];
        u64 w1 = *(u64*)&sW[k * 128 + c4 + 2];
#pragma unroll
        for (int r = 0; r < 8; r++) {
            u64 ap = *(u64*)&sA[(rg * 8 + r) * 64 + k * 2];
            fma2(acc[r][0], ap, w0);
            fma2(acc[r][1], ap, w1);
        }
    }
#pragma unroll
    for (int r = 0; r < 8; r++) {
        int row = r0b + rg * 8 + r;
        *(u64*)&g_c[(size_t)row * 128 + c4]     = acc[r][0];
        *(u64*)&g_c[(size_t)row * 128 + c4 + 2] = acc[r][1];
    }
}

// ---------------- aggregation: one warp per node (sorted edge list) ----------------
__global__ __launch_bounds__(256) void k_agg(const int* __restrict__ srcp) {
    __shared__ int s_eid[8][128];
    int w = threadIdx.x >> 5;
    int lane = threadIdx.x & 31;
    int n = blockIdx.x * 8 + w;
    if (n >= NN) return;
    int start = g_rowptr[n], end = g_rowptr[n + 1];
    int deg = end - start;
    int msort = deg < 128 ? deg : 128;

    for (int j = lane; j < msort; j += 32) s_eid[w][j] = g_eid[start + j];
    __syncwarp();
    for (int pass = 0; pass < msort; pass++) {         // odd-even sort (deterministic order)
        int off = pass & 1;
        for (int j = lane; 2 * j + 1 + off < msort; j += 32) {
            int i0 = 2 * j + off, i1 = i0 + 1;
            int a = s_eid[w][i0], b = s_eid[w][i1];
            if (a > b) { s_eid[w][i0] = b; s_eid[w][i1] = a; }
        }
        __syncwarp();
    }

    float4 base = *(const float4*)&g_a[(size_t)n * 128 + lane * 4];
    float4 bm   = *(const float4*)&g_biasm[lane * 4];
    base.x += bm.x; base.y += bm.y; base.z += bm.z; base.w += bm.w;

    float4 s  = make_float4(0.f, 0.f, 0.f, 0.f);
    float4 sq = make_float4(0.f, 0.f, 0.f, 0.f);
    float4 mx = make_float4(-FMAXV, -FMAXV, -FMAXV, -FMAXV);
    float4 mn = make_float4( FMAXV,  FMAXV,  FMAXV,  FMAXV);

    for (int sl = 0; sl < deg; sl++) {
        int eid = (sl < 128) ? s_eid[w][sl] : __ldg(&g_eid[start + sl]);
        int sn  = __ldg(&srcp[eid]);
        float4 c = *(const float4*)&g_c[(size_t)eid * 128 + lane * 4];
        float4 b = *(const float4*)&g_b[(size_t)sn * 128 + lane * 4];
        float m0 = base.x + b.x + c.x;
        float m1 = base.y + b.y + c.y;
        float m2 = base.z + b.z + c.z;
        float m3 = base.w + b.w + c.w;
        s.x += m0; s.y += m1; s.z += m2; s.w += m3;
        sq.x = fmaf(m0, m0, sq.x); sq.y = fmaf(m1, m1, sq.y);
        sq.z = fmaf(m2, m2, sq.z); sq.w = fmaf(m3, m3, sq.w);
        mx.x = fmaxf(mx.x, m0); mx.y = fmaxf(mx.y, m1); mx.z = fmaxf(mx.z, m2); mx.w = fmaxf(mx.w, m3);
        mn.x = fminf(mn.x, m0); mn.y = fminf(mn.y, m1); mn.z = fminf(mn.z, m2); mn.w = fminf(mn.w, m3);
    }
    if (deg == 0) {
        mx = make_float4(0.f, 0.f, 0.f, 0.f);
        mn = make_float4(0.f, 0.f, 0.f, 0.f);
    }
    float cs = (float)(deg > 0 ? deg : 1);
    float inv = 1.0f / cs;
    float4 mean = make_float4(s.x * inv, s.y * inv, s.z * inv, s.w * inv);
    float4 msq  = make_float4(sq.x * inv, sq.y * inv, sq.z * inv, sq.w * inv);
    float4 sd;
    sd.x = sqrtf(fmaxf(msq.x - mean.x * mean.x, 0.f) + 1e-5f);
    sd.y = sqrtf(fmaxf(msq.y - mean.y * mean.y, 0.f) + 1e-5f);
    sd.z = sqrtf(fmaxf(msq.z - mean.z * mean.z, 0.f) + 1e-5f);
    sd.w = sqrtf(fmaxf(msq.w - mean.w * mean.w, 0.f) + 1e-5f);

    int t = (lane * 4) >> 5, g0 = (lane * 4) & 31;
    float* aggp = &g_agg[(size_t)n * 512 + t * 128 + g0];
    *(float4*)&aggp[0]  = mean;
    *(float4*)&aggp[32] = mx;
    *(float4*)&aggp[64] = mn;
    *(float4*)&aggp[96] = sd;

    if (lane == 0) {
        float avg = g_avglog;
        float logd = logf((float)deg + 1.0f);
        g_s1[n] = logd / avg;
        g_s2[n] = (deg == 0) ? 1.0f : (avg / logd);
    }
}

// ---------------- post-MLP (f32x2): y = xt@W0 + agg@W1 + s1*(agg@W2) + s2*(agg@W3) + b ----------------
__global__ __launch_bounds__(256) void k_post(const float* __restrict__ x,
                                              const float* __restrict__ W_post,
                                              const float* __restrict__ b_post) {
    __shared__ float s_w0[32 * 32];
    __shared__ float s_w1[32 * 32];
    __shared__ float s_w2[32 * 32];
    __shared__ float s_w3[32 * 32];
    __shared__ float s_xt[64 * 66];   // dup pairs, stride 66
    __shared__ float s_ag[64 * 66];   // dup pairs, stride 66
    __shared__ float s_c1[64], s_c2[64];

    int t  = blockIdx.y;
    int n0 = blockIdx.x * 64;
    int tid = threadIdx.x;
    int cp = tid & 15;               // column pair: cols 2cp, 2cp+1
    int g0 = cp * 2;
    int rslot = tid >> 4;            // 0..15, 4 rows each
    const float* Wt = W_post + (size_t)t * 416 * 32;

    for (int i = tid; i < 32 * 32; i += 256) s_w0[i] = Wt[i];
    for (int i = tid; i < 64 * 32; i += 256) {
        int r = i >> 5, f = i & 31;
        float v = x[(size_t)(n0 + r) * 128 + t * 32 + f];
        *(float2*)&s_xt[r * 66 + f * 2] = make_float2(v, v);
    }
    if (tid < 64) { s_c1[tid] = g_s1[n0 + tid]; s_c2[tid] = g_s2[n0 + tid]; }
    __syncthreads();

    u64 acc1[4], acc2[4], acc3[4];
#pragma unroll
    for (int r = 0; r < 4; r++) { acc1[r] = 0ull; acc2[r] = 0ull; acc3[r] = 0ull; }

    // xt @ W0 into acc1
#pragma unroll 8
    for (int f = 0; f < 32; f++) {
        u64 w0p = *(u64*)&s_w0[f * 32 + g0];
#pragma unroll
        for (int r = 0; r < 4; r++) {
            u64 ap = *(u64*)&s_xt[(rslot * 4 + r) * 66 + f * 2];
            fma2(acc1[r], ap, w0p);
        }
    }

    for (int kt = 0; kt < 4; kt++) {
        int k0 = kt * 32;
        __syncthreads();
        for (int i = tid; i < 32 * 32; i += 256) {
            int kk = i >> 5, gg = i & 31;
            s_w1[i] = Wt[(32 + k0 + kk) * 32 + gg];
            s_w2[i] = Wt[(160 + k0 + kk) * 32 + gg];
            s_w3[i] = Wt[(288 + k0 + kk) * 32 + gg];
        }
        for (int i = tid; i < 64 * 32; i += 256) {
            int r = i >> 5, kk = i & 31;
            float v = g_agg[(size_t)(n0 + r) * 512 + t * 128 + k0 + kk];
            *(float2*)&s_ag[r * 66 + kk * 2] = make_float2(v, v);
        }
        __syncthreads();
#pragma unroll 8
        for (int k = 0; k < 32; k++) {
            u64 w1p = *(u64*)&s_w1[k * 32 + g0];
            u64 w2p = *(u64*)&s_w2[k * 32 + g0];
            u64 w3p = *(u64*)&s_w3[k * 32 + g0];
#pragma unroll
            for (int r = 0; r < 4; r++) {
                u64 ap = *(u64*)&s_ag[(rslot * 4 + r) * 66 + k * 2];
                fma2(acc1[r], ap, w1p);
                fma2(acc2[r], ap, w2p);
                fma2(acc3[r], ap, w3p);
            }
        }
    }

    float bp0 = b_post[t * 32 + g0];
    float bp1 = b_post[t * 32 + g0 + 1];
#pragma unroll
    for (int r = 0; r < 4; r++) {
        int row = rslot * 4 + r;
        float c1 = s_c1[row], c2 = s_c2[row];
        float y0 = f2lo(acc1[r]) + c1 * f2lo(acc2[r]) + c2 * f2lo(acc3[r]) + bp0;
        float y1 = f2hi(acc1[r]) + c1 * f2hi(acc2[r]) + c2 * f2hi(acc3[r]) + bp1;
        *(float2*)&g_Z[(size_t)(n0 + row) * 128 + t * 32 + g0] = make_float2(y0, y1);
    }
}

// ---------------- final (f32x2): out = Z @ W_lin^T + b_lin + x ----------------
__global__ __launch_bounds__(256) void k_final(const float* __restrict__ x,
                                               const float* __restrict__ b_lin,
                                               float* __restrict__ out) {
    __shared__ float sA[64 * 64];    // dup pairs per 32-k chunk, stride 64 (broadcast)
    __shared__ float sW[32 * 128];
    int r0b = blockIdx.x * 64;
    int tid = threadIdx.x;
    int c4 = (tid & 31) * 4;
    int rg = tid >> 5;
    u64 acc[8][2];
#pragma unroll
    for (int r = 0; r < 8; r++) { acc[r][0] = 0ull; acc[r][1] = 0ull; }

    for (int k0 = 0; k0 < 128; k0 += 32) {
        __syncthreads();
        for (int i = tid; i < 64 * 8; i += 256) {
            int r = i >> 3, kg = (i & 7) * 4;
            float4 v = *(const float4*)&g_Z[(size_t)(r0b + r) * 128 + k0 + kg];
            *(float4*)&sA[r * 64 + kg * 2]     = make_float4(v.x, v.x, v.y, v.y);
            *(float4*)&sA[r * 64 + kg * 2 + 4] = make_float4(v.z, v.z, v.w, v.w);
        }
        for (int i = tid; i < 32 * 32; i += 256) {
            int kk = i >> 5, cg = (i & 31) * 4;
            *(float4*)&sW[kk * 128 + cg] = *(const float4*)&g_WlinT[(k0 + kk) * 128 + cg];
        }
        __syncthreads();
#pragma unroll
        for (int k = 0; k < 32; k++) {
            u64 w0 = *(u64*)&sW[k * 128 + c4];
            u64 w1 = *(u64*)&sW[k * 128 + c4 + 2];
#pragma unroll
            for (int r = 0; r < 8; r++) {
                u64 ap = *(u64*)&sA[(rg * 8 + r) * 64 + k * 2];
                fma2(acc[r][0], ap, w0);
                fma2(acc[r][1], ap, w1);
            }
        }
    }
#pragma unroll
    for (int r = 0; r < 8; r++) {
        int row = r0b + rg * 8 + r;
        float4 bl = *(const float4*)&b_lin[c4];
        float4 xr = *(const float4*)&x[(size_t)row * 128 + c4];
        float4 y;
        y.x = f2lo(acc[r][0]) + bl.x + xr.x;
        y.y = f2hi(acc[r][0]) + bl.y + xr.y;
        y.z = f2lo(acc[r][1]) + bl.z + xr.z;
        y.w = f2hi(acc[r][1]) + bl.w + xr.w;
        *(float4*)&out[(size_t)row * 128 + c4] = y;
    }
}

// ---------------- launch ----------------
extern "C" void kernel_launch(void* const* d_in, const int* in_sizes, int n_in,
                              void* d_out, int out_size) {
    const float* x         = (const float*)d_in[0];
    const float* edge_attr = (const float*)d_in[1];
    const int*   edge_idx  = (const int*)d_in[2];
    const float* W_edge    = (const float*)d_in[3];
    const float* b_edge    = (const float*)d_in[4];
    const float* W_pre     = (const float*)d_in[5];
    const float* b_pre     = (const float*)d_in[6];
    const float* W_post    = (const float*)d_in[7];
    const float* b_post    = (const float*)d_in[8];
    const float* W_lin     = (const float*)d_in[9];
    const float* b_lin     = (const float*)d_in[10];
    float* out = (float*)d_out;

    const int* srcp = edge_idx;
    const int* dstp = edge_idx + EE;

    k_zero<<<NN / 256, 256>>>();
    k_prep<<<64, 256>>>(W_edge, W_lin, W_pre, b_pre, b_edge);
    k_hist<<<EE / 256, 256>>>(dstp);
    k_scan1<<<256, 256>>>();
    k_scan2<<<1, 256>>>();
    k_scan3<<<256, 256>>>();
    k_scatter<<<EE / 256, 256>>>(dstp);
    k_ab<<<(NN * 128) / 256, 256>>>(x, W_pre);
    k_egemm<<<EE / 128, 256>>>(edge_attr);
    k_cgemm<<<EE / 64, 256>>>(W_pre);
    k_agg<<<NN / 8, 256>>>(srcp);
    k_post<<<dim3(NN / 64, 4), 256>>>(x, W_post, b_post);
    k_final<<<NN / 64, 256>>>(x, b_lin, out);
}

// round 4
// speedup vs baseline: 1.3607x; 1.3607x over previous
#include <cuda_runtime.h>
#include <cuda_bf16.h>
#include <math.h>
#include <stdint.h>
#include <stddef.h>

#define NN 65536
#define EE 1048576
#define FMAXV 3.402823466e38f

typedef unsigned long long u64;

__device__ __forceinline__ void fma2(u64& d, u64 a, u64 b) {
    asm("fma.rn.f32x2 %0, %1, %2, %3;" : "=l"(d) : "l"(a), "l"(b), "l"(d));
}
__device__ __forceinline__ float f2lo(u64 v) { return __uint_as_float((unsigned)v); }
__device__ __forceinline__ float f2hi(u64 v) { return __uint_as_float((unsigned)(v >> 32)); }

// ---------------- static device scratch (no allocations) ----------------
__device__ float g_e[(size_t)EE * 32];      // edge_attr @ W_edge^T (no bias)
__device__ float g_c[(size_t)EE * 128];     // e @ Wpre_edgepart
__device__ float g_a[(size_t)NN * 128];     // dst-side node pre-part
__device__ float g_b[(size_t)NN * 128];     // src-side node pre-part
__device__ float g_agg[(size_t)NN * 512];   // per node/tower: [mean|mx|mn|std] x32
__device__ float g_Z[(size_t)NN * 128];     // post-MLP output
__device__ float g_s1[NN];
__device__ float g_s2[NN];
__device__ int   g_cnt[NN];
__device__ int   g_fill[NN];
__device__ int   g_rowptr[NN + 1];
__device__ int   g_eid[EE];
__device__ int   g_bsum[256];
__device__ float g_biasm[128];
__device__ float g_WedgeT[128 * 32];        // [k][f]
__device__ float g_WlinT[128 * 128];        // [k][c]
__device__ float g_avglog;

// ---------------- setup ----------------
__global__ void k_zero(void) {
    int i = blockIdx.x * 256 + threadIdx.x;
    if (i < NN) { g_cnt[i] = 0; g_fill[i] = 0; }
}

__global__ void k_prep(const float* __restrict__ W_edge, const float* __restrict__ W_lin,
                       const float* __restrict__ W_pre, const float* __restrict__ b_pre,
                       const float* __restrict__ b_edge) {
    int i = blockIdx.x * 256 + threadIdx.x;
    if (i < 128 * 32) {                      // WedgeT[k*32+f] = W_edge[f*128+k]
        int k = i >> 5, f = i & 31;
        g_WedgeT[i] = W_edge[f * 128 + k];
    }
    if (i < 128 * 128) {                     // WlinT[k*128+c] = W_lin[c*128+k]
        int k = i >> 7, c = i & 127;
        g_WlinT[i] = W_lin[c * 128 + k];
    }
    if (i < 128) {                           // biasm = b_pre + Wpre_e^T b_edge
        int t = i >> 5, g = i & 31;
        float s = b_pre[i];
        for (int j = 0; j < 32; j++)
            s += b_edge[j] * W_pre[t * 3072 + (64 + j) * 32 + g];
        g_biasm[i] = s;
    }
    if (i == 0) {
        const double cnts[6] = {108477.0, 299931.0, 180702.0, 10767.0, 3.0, 2.0};
        double num = 0.0, den = 0.0;
        for (int d = 0; d < 6; d++) { num += cnts[d] * log((double)(d + 1) + 1.0); den += cnts[d]; }
        g_avglog = (float)(num / den);
    }
}

// ---------------- CSR build ----------------
__global__ void k_hist(const int* __restrict__ dst) {
    int i = blockIdx.x * 256 + threadIdx.x;
    if (i < EE) atomicAdd(&g_cnt[dst[i]], 1);
}

__global__ void k_scan1(void) {
    int b = blockIdx.x, t = threadIdx.x;
    int gi = b * 256 + t;
    int v = g_cnt[gi];
    int lane = t & 31, w = t >> 5;
    int incl = v;
#pragma unroll
    for (int off = 1; off < 32; off <<= 1) {
        int u = __shfl_up_sync(0xffffffffu, incl, off);
        if (lane >= off) incl += u;
    }
    __shared__ int wtot[8];
    __shared__ int woff[8];
    if (lane == 31) wtot[w] = incl;
    __syncthreads();
    if (t == 0) {
        int run = 0;
        for (int i = 0; i < 8; i++) { woff[i] = run; run += wtot[i]; }
        g_bsum[b] = run;
    }
    __syncthreads();
    g_rowptr[gi] = woff[w] + incl - v;
}

__global__ void k_scan2(void) {
    int t = threadIdx.x;
    int v = g_bsum[t];
    int lane = t & 31, w = t >> 5;
    int incl = v;
#pragma unroll
    for (int off = 1; off < 32; off <<= 1) {
        int u = __shfl_up_sync(0xffffffffu, incl, off);
        if (lane >= off) incl += u;
    }
    __shared__ int wtot[8];
    __shared__ int woff[8];
    if (lane == 31) wtot[w] = incl;
    __syncthreads();
    if (t == 0) {
        int run = 0;
        for (int i = 0; i < 8; i++) { woff[i] = run; run += wtot[i]; }
    }
    __syncthreads();
    g_bsum[t] = woff[w] + incl - v;
    if (t == 0) g_rowptr[NN] = EE;
}

__global__ void k_scan3(void) {
    int b = blockIdx.x, t = threadIdx.x;
    g_rowptr[b * 256 + t] += g_bsum[b];
}

__global__ void k_scatter(const int* __restrict__ dst) {
    int i = blockIdx.x * 256 + threadIdx.x;
    if (i < EE) {
        int d = dst[i];
        int slot = g_rowptr[d] + atomicAdd(&g_fill[d], 1);
        g_eid[slot] = i;
    }
}

// ---------------- node pre-parts ----------------
__global__ void k_ab(const float* __restrict__ x, const float* __restrict__ W_pre) {
    int i = blockIdx.x * 256 + threadIdx.x;
    if (i >= NN * 128) return;
    int n = i >> 7, ch = i & 127;
    int t = ch >> 5, g = ch & 31;
    const float* xr = x + (size_t)n * 128 + t * 32;
    const float* wa = W_pre + t * 3072 + g;
    const float* wb = wa + 1024;
    float a = 0.f, b = 0.f;
#pragma unroll
    for (int f = 0; f < 32; f++) {
        float xv = __ldg(&xr[f]);
        a = fmaf(xv, __ldg(&wa[f * 32]), a);
        b = fmaf(xv, __ldg(&wb[f * 32]), b);
    }
    g_a[i] = a; g_b[i] = b;
}

// ---------------- e-GEMM: e[E,32] = edge_attr[E,128] @ WedgeT (row-pair FFMA2) ----------------
__global__ __launch_bounds__(256) void k_egemm(const float* __restrict__ ea) {
    __shared__ float2 sP[32 * 129];   // [k][rowpair], stride 129 pairs
    __shared__ float  sWd[32 * 68];   // duplicated weights [k][2f], stride 68 floats
    int r0b = blockIdx.x * 256;
    int tid = threadIdx.x;
    int c4 = (tid & 7) * 4;
    int rg = tid >> 3;                // 0..31 -> row pairs rg*4 .. rg*4+3
    u64 acc[4][4];
#pragma unroll
    for (int p = 0; p < 4; p++)
#pragma unroll
        for (int c = 0; c < 4; c++) acc[p][c] = 0ull;

    for (int k0 = 0; k0 < 128; k0 += 32) {
        __syncthreads();
        for (int i = tid; i < 128 * 8; i += 256) {     // stage A as row pairs, k-major
            int rp = i >> 3, kg = (i & 7) * 4;
            const float* b0 = &ea[(size_t)(r0b + 2 * rp) * 128 + k0 + kg];
            float4 a0 = *(const float4*)b0;
            float4 a1 = *(const float4*)(b0 + 128);
            sP[(kg + 0) * 129 + rp] = make_float2(a0.x, a1.x);
            sP[(kg + 1) * 129 + rp] = make_float2(a0.y, a1.y);
            sP[(kg + 2) * 129 + rp] = make_float2(a0.z, a1.z);
            sP[(kg + 3) * 129 + rp] = make_float2(a0.w, a1.w);
        }
        for (int i = tid; i < 32 * 32; i += 256) {     // duplicated W (tiny)
            int kk = i >> 5, f = i & 31;
            float w = g_WedgeT[(k0 + kk) * 32 + f];
            sWd[kk * 68 + 2 * f]     = w;
            sWd[kk * 68 + 2 * f + 1] = w;
        }
        __syncthreads();
#pragma unroll
        for (int k = 0; k < 32; k++) {
            const float* wb = &sWd[k * 68 + 2 * c4];
            u64 w0 = *(const u64*)(wb + 0);
            u64 w1 = *(const u64*)(wb + 2);
            u64 w2 = *(const u64*)(wb + 4);
            u64 w3 = *(const u64*)(wb + 6);
#pragma unroll
            for (int p = 0; p < 4; p++) {
                u64 ap = *(const u64*)&sP[k * 129 + rg * 4 + p];
                fma2(acc[p][0], ap, w0);
                fma2(acc[p][1], ap, w1);
                fma2(acc[p][2], ap, w2);
                fma2(acc[p][3], ap, w3);
            }
        }
    }
#pragma unroll
    for (int p = 0; p < 4; p++) {
        int row0 = r0b + (rg * 4 + p) * 2;
        float4 lo = make_float4(f2lo(acc[p][0]), f2lo(acc[p][1]), f2lo(acc[p][2]), f2lo(acc[p][3]));
        float4 hi = make_float4(f2hi(acc[p][0]), f2hi(acc[p][1]), f2hi(acc[p][2]), f2hi(acc[p][3]));
        *(float4*)&g_e[(size_t)row0 * 32 + c4]       = lo;
        *(float4*)&g_e[(size_t)(row0 + 1) * 32 + c4] = hi;
    }
}

// ---------------- c-GEMM: c[E,128] = e[E,32] @ Wpre_edgepart (row-pair FFMA2) ----------------
__global__ __launch_bounds__(256) void k_cgemm(const float* __restrict__ W_pre) {
    __shared__ float2 sP[32 * 33];     // [k][rowpair], 32 pairs (64 rows)
    __shared__ float  sWd[32 * 264];   // duplicated [k][2o], stride 264 floats (16B aligned)
    int r0b = blockIdx.x * 64;
    int tid = threadIdx.x;
    int c4 = (tid & 31) * 4;
    int prg = tid >> 5;                // 0..7 -> pairs prg*4 .. prg*4+3

    for (int i = tid; i < 32 * 128; i += 256) {    // duplicated W
        int k = i >> 7, o = i & 127;
        int t = o >> 5, g = o & 31;
        float w = W_pre[t * 3072 + (64 + k) * 32 + g];
        sWd[k * 264 + 2 * o]     = w;
        sWd[k * 264 + 2 * o + 1] = w;
    }
    {
        int i = tid;                                // 256 items: 32 pairs x 8 kgroups
        int rp = i >> 3, kg = (i & 7) * 4;
        const float* b0 = &g_e[(size_t)(r0b + 2 * rp) * 32 + kg];
        float4 a0 = *(const float4*)b0;
        float4 a1 = *(const float4*)(b0 + 32);
        sP[(kg + 0) * 33 + rp] = make_float2(a0.x, a1.x);
        sP[(kg + 1) * 33 + rp] = make_float2(a0.y, a1.y);
        sP[(kg + 2) * 33 + rp] = make_float2(a0.z, a1.z);
        sP[(kg + 3) * 33 + rp] = make_float2(a0.w, a1.w);
    }
    __syncthreads();

    u64 acc[4][4];
#pragma unroll
    for (int p = 0; p < 4; p++)
#pragma unroll
        for (int c = 0; c < 4; c++) acc[p][c] = 0ull;

#pragma unroll
    for (int k = 0; k < 32; k++) {
        const float* wb = &sWd[k * 264 + 2 * c4];
        u64 w0 = *(const u64*)(wb + 0);
        u64 w1 = *(const u64*)(wb + 2);
        u64 w2 = *(const u64*)(wb + 4);
        u64 w3 = *(const u64*)(wb + 6);
#pragma unroll
        for (int p = 0; p < 4; p++) {
            u64 ap = *(const u64*)&sP[k * 33 + prg * 4 + p];
            fma2(acc[p][0], ap, w0);
            fma2(acc[p][1], ap, w1);
            fma2(acc[p][2], ap, w2);
            fma2(acc[p][3], ap, w3);
        }
    }
#pragma unroll
    for (int p = 0; p < 4; p++) {
        int row0 = r0b + (prg * 4 + p) * 2;
        float4 lo = make_float4(f2lo(acc[p][0]), f2lo(acc[p][1]), f2lo(acc[p][2]), f2lo(acc[p][3]));
        float4 hi = make_float4(f2hi(acc[p][0]), f2hi(acc[p][1]), f2hi(acc[p][2]), f2hi(acc[p][3]));
        *(float4*)&g_c[(size_t)row0 * 128 + c4]       = lo;
        *(float4*)&g_c[(size_t)(row0 + 1) * 128 + c4] = hi;
    }
}

// ---------------- aggregation: one warp per node (sorted edge list) ----------------
__global__ __launch_bounds__(256) void k_agg(const int* __restrict__ srcp) {
    __shared__ int s_eid[8][128];
    int w = threadIdx.x >> 5;
    int lane = threadIdx.x & 31;
    int n = blockIdx.x * 8 + w;
    if (n >= NN) return;
    int start = g_rowptr[n], end = g_rowptr[n + 1];
    int deg = end - start;
    int msort = deg < 128 ? deg : 128;

    for (int j = lane; j < msort; j += 32) s_eid[w][j] = g_eid[start + j];
    __syncwarp();
    for (int pass = 0; pass < msort; pass++) {
        int off = pass & 1;
        for (int j = lane; 2 * j + 1 + off < msort; j += 32) {
            int i0 = 2 * j + off, i1 = i0 + 1;
            int a = s_eid[w][i0], b = s_eid[w][i1];
            if (a > b) { s_eid[w][i0] = b; s_eid[w][i1] = a; }
        }
        __syncwarp();
    }

    float4 base = *(const float4*)&g_a[(size_t)n * 128 + lane * 4];
    float4 bm   = *(const float4*)&g_biasm[lane * 4];
    base.x += bm.x; base.y += bm.y; base.z += bm.z; base.w += bm.w;

    float4 s  = make_float4(0.f, 0.f, 0.f, 0.f);
    float4 sq = make_float4(0.f, 0.f, 0.f, 0.f);
    float4 mx = make_float4(-FMAXV, -FMAXV, -FMAXV, -FMAXV);
    float4 mn = make_float4( FMAXV,  FMAXV,  FMAXV,  FMAXV);

    for (int sl = 0; sl < deg; sl++) {
        int eid = (sl < 128) ? s_eid[w][sl] : __ldg(&g_eid[start + sl]);
        int sn  = __ldg(&srcp[eid]);
        float4 c = *(const float4*)&g_c[(size_t)eid * 128 + lane * 4];
        float4 b = *(const float4*)&g_b[(size_t)sn * 128 + lane * 4];
        float m0 = base.x + b.x + c.x;
        float m1 = base.y + b.y + c.y;
        float m2 = base.z + b.z + c.z;
        float m3 = base.w + b.w + c.w;
        s.x += m0; s.y += m1; s.z += m2; s.w += m3;
        sq.x = fmaf(m0, m0, sq.x); sq.y = fmaf(m1, m1, sq.y);
        sq.z = fmaf(m2, m2, sq.z); sq.w = fmaf(m3, m3, sq.w);
        mx.x = fmaxf(mx.x, m0); mx.y = fmaxf(mx.y, m1); mx.z = fmaxf(mx.z, m2); mx.w = fmaxf(mx.w, m3);
        mn.x = fminf(mn.x, m0); mn.y = fminf(mn.y, m1); mn.z = fminf(mn.z, m2); mn.w = fminf(mn.w, m3);
    }
    if (deg == 0) {
        mx = make_float4(0.f, 0.f, 0.f, 0.f);
        mn = make_float4(0.f, 0.f, 0.f, 0.f);
    }
    float cs = (float)(deg > 0 ? deg : 1);
    float inv = 1.0f / cs;
    float4 mean = make_float4(s.x * inv, s.y * inv, s.z * inv, s.w * inv);
    float4 msq  = make_float4(sq.x * inv, sq.y * inv, sq.z * inv, sq.w * inv);
    float4 sd;
    sd.x = sqrtf(fmaxf(msq.x - mean.x * mean.x, 0.f) + 1e-5f);
    sd.y = sqrtf(fmaxf(msq.y - mean.y * mean.y, 0.f) + 1e-5f);
    sd.z = sqrtf(fmaxf(msq.z - mean.z * mean.z, 0.f) + 1e-5f);
    sd.w = sqrtf(fmaxf(msq.w - mean.w * mean.w, 0.f) + 1e-5f);

    int t = (lane * 4) >> 5, g0 = (lane * 4) & 31;
    float* aggp = &g_agg[(size_t)n * 512 + t * 128 + g0];
    *(float4*)&aggp[0]  = mean;
    *(float4*)&aggp[32] = mx;
    *(float4*)&aggp[64] = mn;
    *(float4*)&aggp[96] = sd;

    if (lane == 0) {
        float avg = g_avglog;
        float logd = logf((float)deg + 1.0f);
        g_s1[n] = logd / avg;
        g_s2[n] = (deg == 0) ? 1.0f : (avg / logd);
    }
}

// ---------------- post-MLP (R2 scalar version) ----------------
__global__ __launch_bounds__(256) void k_post(const float* __restrict__ x,
                                              const float* __restrict__ W_post,
                                              const float* __restrict__ b_post) {
    __shared__ float s_w0[32 * 32];
    __shared__ float s_w1[32 * 32];
    __shared__ float s_w2[32 * 32];
    __shared__ float s_w3[32 * 32];
    __shared__ float s_xt[64 * 32];
    __shared__ float s_ag[64 * 32];
    __shared__ float s_c1[64], s_c2[64];

    int t  = blockIdx.y;
    int n0 = blockIdx.x * 64;
    int tid = threadIdx.x;
    int g = tid & 31;
    int rslot = tid >> 5;
    const float* Wt = W_post + (size_t)t * 416 * 32;

    for (int i = tid; i < 32 * 32; i += 256) s_w0[i] = Wt[i];
    for (int i = tid; i < 64 * 32; i += 256) {
        int r = i >> 5, f = i & 31;
        s_xt[i] = x[(size_t)(n0 + r) * 128 + t * 32 + f];
    }
    if (tid < 64) { s_c1[tid] = g_s1[n0 + tid]; s_c2[tid] = g_s2[n0 + tid]; }
    __syncthreads();

    float acc1[8], acc2[8], acc3[8];
#pragma unroll
    for (int r = 0; r < 8; r++) { acc1[r] = 0.f; acc2[r] = 0.f; acc3[r] = 0.f; }

#pragma unroll 4
    for (int f = 0; f < 32; f++) {
        float w0 = s_w0[f * 32 + g];
#pragma unroll
        for (int r = 0; r < 8; r++)
            acc1[r] = fmaf(s_xt[(rslot * 8 + r) * 32 + f], w0, acc1[r]);
    }

    for (int kt = 0; kt < 4; kt++) {
        int k0 = kt * 32;
        __syncthreads();
        for (int i = tid; i < 32 * 32; i += 256) {
            int kk = i >> 5, gg = i & 31;
            s_w1[i] = Wt[(32 + k0 + kk) * 32 + gg];
            s_w2[i] = Wt[(160 + k0 + kk) * 32 + gg];
            s_w3[i] = Wt[(288 + k0 + kk) * 32 + gg];
        }
        for (int i = tid; i < 64 * 32; i += 256) {
            int r = i >> 5, kk = i & 31;
            s_ag[i] = g_agg[(size_t)(n0 + r) * 512 + t * 128 + k0 + kk];
        }
        __syncthreads();
#pragma unroll 4
        for (int k = 0; k < 32; k++) {
            float w1 = s_w1[k * 32 + g];
            float w2 = s_w2[k * 32 + g];
            float w3 = s_w3[k * 32 + g];
#pragma unroll
            for (int r = 0; r < 8; r++) {
                float a = s_ag[(rslot * 8 + r) * 32 + k];
                acc1[r] = fmaf(a, w1, acc1[r]);
                acc2[r] = fmaf(a, w2, acc2[r]);
                acc3[r] = fmaf(a, w3, acc3[r]);
            }
        }
    }

    float bp = b_post[t * 32 + g];
#pragma unroll
    for (int r = 0; r < 8; r++) {
        int row = rslot * 8 + r;
        float y = acc1[r] + s_c1[row] * acc2[r] + s_c2[row] * acc3[r] + bp;
        g_Z[(size_t)(n0 + row) * 128 + t * 32 + g] = y;
    }
}

// ---------------- final (R2 scalar version) ----------------
__global__ __launch_bounds__(256) void k_final(const float* __restrict__ x,
                                               const float* __restrict__ b_lin,
                                               float* __restrict__ out) {
    __shared__ float sA[64 * 36];
    __shared__ float sW[32 * 128];
    int r0b = blockIdx.x * 64;
    int tid = threadIdx.x;
    int c4 = (tid & 31) * 4;
    int rg = tid >> 5;
    float4 acc[8];
#pragma unroll
    for (int r = 0; r < 8; r++) acc[r] = make_float4(0.f, 0.f, 0.f, 0.f);

    for (int k0 = 0; k0 < 128; k0 += 32) {
        __syncthreads();
        for (int i = tid; i < 64 * 8; i += 256) {
            int r = i >> 3, kg = (i & 7) * 4;
            *(float4*)&sA[r * 36 + kg] = *(const float4*)&g_Z[(size_t)(r0b + r) * 128 + k0 + kg];
        }
        for (int i = tid; i < 32 * 32; i += 256) {
            int kk = i >> 5, cg = (i & 31) * 4;
            *(float4*)&sW[kk * 128 + cg] = *(const float4*)&g_WlinT[(k0 + kk) * 128 + cg];
        }
        __syncthreads();
#pragma unroll
        for (int k4 = 0; k4 < 8; k4++) {
            float4 w0 = *(float4*)&sW[(k4 * 4 + 0) * 128 + c4];
            float4 w1 = *(float4*)&sW[(k4 * 4 + 1) * 128 + c4];
            float4 w2 = *(float4*)&sW[(k4 * 4 + 2) * 128 + c4];
            float4 w3 = *(float4*)&sW[(k4 * 4 + 3) * 128 + c4];
#pragma unroll
            for (int r = 0; r < 8; r++) {
                float4 a = *(float4*)&sA[(rg * 8 + r) * 36 + k4 * 4];
                acc[r].x = fmaf(a.x, w0.x, fmaf(a.y, w1.x, fmaf(a.z, w2.x, fmaf(a.w, w3.x, acc[r].x))));
                acc[r].y = fmaf(a.x, w0.y, fmaf(a.y, w1.y, fmaf(a.z, w2.y, fmaf(a.w, w3.y, acc[r].y))));
                acc[r].z = fmaf(a.x, w0.z, fmaf(a.y, w1.z, fmaf(a.z, w2.z, fmaf(a.w, w3.z, acc[r].z))));
                acc[r].w = fmaf(a.x, w0.w, fmaf(a.y, w1.w, fmaf(a.z, w2.w, fmaf(a.w, w3.w, acc[r].w))));
            }
        }
    }
#pragma unroll
    for (int r = 0; r < 8; r++) {
        int row = r0b + rg * 8 + r;
        float4 bl = *(const float4*)&b_lin[c4];
        float4 xr = *(const float4*)&x[(size_t)row * 128 + c4];
        acc[r].x += bl.x + xr.x;
        acc[r].y += bl.y + xr.y;
        acc[r].z += bl.z + xr.z;
        acc[r].w += bl.w + xr.w;
        *(float4*)&out[(size_t)row * 128 + c4] = acc[r];
    }
}

// ---------------- launch ----------------
extern "C" void kernel_launch(void* const* d_in, const int* in_sizes, int n_in,
                              void* d_out, int out_size) {
    const float* x         = (const float*)d_in[0];
    const float* edge_attr = (const float*)d_in[1];
    const int*   edge_idx  = (const int*)d_in[2];
    const float* W_edge    = (const float*)d_in[3];
    const float* b_edge    = (const float*)d_in[4];
    const float* W_pre     = (const float*)d_in[5];
    const float* b_pre     = (const float*)d_in[6];
    const float* W_post    = (const float*)d_in[7];
    const float* b_post    = (const float*)d_in[8];
    const float* W_lin     = (const float*)d_in[9];
    const float* b_lin     = (const float*)d_in[10];
    float* out = (float*)d_out;

    const int* srcp = edge_idx;
    const int* dstp = edge_idx + EE;

    k_zero<<<NN / 256, 256>>>();
    k_prep<<<64, 256>>>(W_edge, W_lin, W_pre, b_pre, b_edge);
    k_hist<<<EE / 256, 256>>>(dstp);
    k_scan1<<<256, 256>>>();
    k_scan2<<<1, 256>>>();
    k_scan3<<<256, 256>>>();
    k_scatter<<<EE / 256, 256>>>(dstp);
    k_ab<<<(NN * 128) / 256, 256>>>(x, W_pre);
    k_egemm<<<EE / 256, 256>>>(edge_attr);
    k_cgemm<<<EE / 64, 256>>>(W_pre);
    k_agg<<<NN / 8, 256>>>(srcp);
    k_post<<<dim3(NN / 64, 4), 256>>>(x, W_post, b_post);
    k_final<<<NN / 64, 256>>>(x, b_lin, out);
}

// round 5
// speedup vs baseline: 1.5791x; 1.1605x over previous
#include <cuda_runtime.h>
#include <cuda_bf16.h>
#include <math.h>
#include <stdint.h>
#include <stddef.h>

#define NN 65536
#define EE 1048576
#define FMAXV 3.402823466e38f

// ---------------- static device scratch (no allocations) ----------------
__device__ float g_e[(size_t)EE * 32];      // edge_attr @ W_edge^T (no bias)
__device__ float g_c[(size_t)EE * 128];     // e @ Wpre_edgepart
__device__ float g_a[(size_t)NN * 128];     // dst-side node pre-part
__device__ float g_b[(size_t)NN * 128];     // src-side node pre-part
__device__ float g_agg[(size_t)NN * 512];   // per node/tower: [mean|mx|mn|std] x32
__device__ float g_Z[(size_t)NN * 128];     // post-MLP output
__device__ float g_s1[NN];
__device__ float g_s2[NN];
__device__ int   g_cnt[NN];
__device__ int   g_fill[NN];
__device__ int   g_rowptr[NN + 1];
__device__ int   g_eid[EE];
__device__ int   g_bsum[256];
__device__ float g_biasm[128];
__device__ float g_WedgeT[128 * 32];        // [k][f]
__device__ float g_WlinT[128 * 128];        // [k][c]
__device__ float g_avglog;

// ---------------- setup ----------------
__global__ void k_zero(void) {
    int i = blockIdx.x * 256 + threadIdx.x;
    if (i < NN) { g_cnt[i] = 0; g_fill[i] = 0; }
}

__global__ void k_prep(const float* __restrict__ W_edge, const float* __restrict__ W_lin,
                       const float* __restrict__ W_pre, const float* __restrict__ b_pre,
                       const float* __restrict__ b_edge) {
    int i = blockIdx.x * 256 + threadIdx.x;
    if (i < 128 * 32) {                      // WedgeT[k*32+f] = W_edge[f*128+k]
        int k = i >> 5, f = i & 31;
        g_WedgeT[i] = W_edge[f * 128 + k];
    }
    if (i < 128 * 128) {                     // WlinT[k*128+c] = W_lin[c*128+k]
        int k = i >> 7, c = i & 127;
        g_WlinT[i] = W_lin[c * 128 + k];
    }
    if (i < 128) {                           // biasm = b_pre + Wpre_e^T b_edge
        int t = i >> 5, g = i & 31;
        float s = b_pre[i];
        for (int j = 0; j < 32; j++)
            s += b_edge[j] * W_pre[t * 3072 + (64 + j) * 32 + g];
        g_biasm[i] = s;
    }
    if (i == 0) {
        const double cnts[6] = {108477.0, 299931.0, 180702.0, 10767.0, 3.0, 2.0};
        double num = 0.0, den = 0.0;
        for (int d = 0; d < 6; d++) { num += cnts[d] * log((double)(d + 1) + 1.0); den += cnts[d]; }
        g_avglog = (float)(num / den);
    }
}

// ---------------- CSR build ----------------
__global__ void k_hist(const int* __restrict__ dst) {
    int i = blockIdx.x * 256 + threadIdx.x;
    if (i < EE) atomicAdd(&g_cnt[dst[i]], 1);
}

__global__ void k_scan1(void) {
    int b = blockIdx.x, t = threadIdx.x;
    int gi = b * 256 + t;
    int v = g_cnt[gi];
    int lane = t & 31, w = t >> 5;
    int incl = v;
#pragma unroll
    for (int off = 1; off < 32; off <<= 1) {
        int u = __shfl_up_sync(0xffffffffu, incl, off);
        if (lane >= off) incl += u;
    }
    __shared__ int wtot[8];
    __shared__ int woff[8];
    if (lane == 31) wtot[w] = incl;
    __syncthreads();
    if (t == 0) {
        int run = 0;
        for (int i = 0; i < 8; i++) { woff[i] = run; run += wtot[i]; }
        g_bsum[b] = run;
    }
    __syncthreads();
    g_rowptr[gi] = woff[w] + incl - v;
}

__global__ void k_scan2(void) {
    int t = threadIdx.x;
    int v = g_bsum[t];
    int lane = t & 31, w = t >> 5;
    int incl = v;
#pragma unroll
    for (int off = 1; off < 32; off <<= 1) {
        int u = __shfl_up_sync(0xffffffffu, incl, off);
        if (lane >= off) incl += u;
    }
    __shared__ int wtot[8];
    __shared__ int woff[8];
    if (lane == 31) wtot[w] = incl;
    __syncthreads();
    if (t == 0) {
        int run = 0;
        for (int i = 0; i < 8; i++) { woff[i] = run; run += wtot[i]; }
    }
    __syncthreads();
    g_bsum[t] = woff[w] + incl - v;
    if (t == 0) g_rowptr[NN] = EE;
}

__global__ void k_scan3(void) {
    int b = blockIdx.x, t = threadIdx.x;
    g_rowptr[b * 256 + t] += g_bsum[b];
}

__global__ void k_scatter(const int* __restrict__ dst) {
    int i = blockIdx.x * 256 + threadIdx.x;
    if (i < EE) {
        int d = dst[i];
        int slot = g_rowptr[d] + atomicAdd(&g_fill[d], 1);
        g_eid[slot] = i;
    }
}

// ---------------- node pre-parts ----------------
__global__ void k_ab(const float* __restrict__ x, const float* __restrict__ W_pre) {
    int i = blockIdx.x * 256 + threadIdx.x;
    if (i >= NN * 128) return;
    int n = i >> 7, ch = i & 127;
    int t = ch >> 5, g = ch & 31;
    const float* xr = x + (size_t)n * 128 + t * 32;
    const float* wa = W_pre + t * 3072 + g;
    const float* wb = wa + 1024;
    float a = 0.f, b = 0.f;
#pragma unroll
    for (int f = 0; f < 32; f++) {
        float xv = __ldg(&xr[f]);
        a = fmaf(xv, __ldg(&wa[f * 32]), a);
        b = fmaf(xv, __ldg(&wb[f * 32]), b);
    }
    g_a[i] = a; g_b[i] = b;
}

// ---------------- e-GEMM: e[E,32] = edge_attr[E,128] @ WedgeT (R2 scalar) ----------------
__global__ __launch_bounds__(256) void k_egemm(const float* __restrict__ ea) {
    __shared__ float sA[256 * 36];
    __shared__ float sW[32 * 36];
    int r0b = blockIdx.x * 256;
    int tid = threadIdx.x;
    int c4 = (tid & 7) * 4;
    int rg = tid >> 3;
    float4 acc[8];
#pragma unroll
    for (int r = 0; r < 8; r++) acc[r] = make_float4(0.f, 0.f, 0.f, 0.f);

    for (int k0 = 0; k0 < 128; k0 += 32) {
        __syncthreads();
        for (int i = tid; i < 256 * 8; i += 256) {
            int r = i >> 3, kg = (i & 7) * 4;
            *(float4*)&sA[r * 36 + kg] = *(const float4*)&ea[(size_t)(r0b + r) * 128 + k0 + kg];
        }
        for (int i = tid; i < 32 * 8; i += 256) {
            int kk = i >> 3, fg = (i & 7) * 4;
            *(float4*)&sW[kk * 36 + fg] = *(const float4*)&g_WedgeT[(k0 + kk) * 32 + fg];
        }
        __syncthreads();
#pragma unroll
        for (int k4 = 0; k4 < 8; k4++) {
            float4 w0 = *(float4*)&sW[(k4 * 4 + 0) * 36 + c4];
            float4 w1 = *(float4*)&sW[(k4 * 4 + 1) * 36 + c4];
            float4 w2 = *(float4*)&sW[(k4 * 4 + 2) * 36 + c4];
            float4 w3 = *(float4*)&sW[(k4 * 4 + 3) * 36 + c4];
#pragma unroll
            for (int r = 0; r < 8; r++) {
                float4 a = *(float4*)&sA[(rg * 8 + r) * 36 + k4 * 4];
                acc[r].x = fmaf(a.x, w0.x, fmaf(a.y, w1.x, fmaf(a.z, w2.x, fmaf(a.w, w3.x, acc[r].x))));
                acc[r].y = fmaf(a.x, w0.y, fmaf(a.y, w1.y, fmaf(a.z, w2.y, fmaf(a.w, w3.y, acc[r].y))));
                acc[r].z = fmaf(a.x, w0.z, fmaf(a.y, w1.z, fmaf(a.z, w2.z, fmaf(a.w, w3.z, acc[r].z))));
                acc[r].w = fmaf(a.x, w0.w, fmaf(a.y, w1.w, fmaf(a.z, w2.w, fmaf(a.w, w3.w, acc[r].w))));
            }
        }
    }
#pragma unroll
    for (int r = 0; r < 8; r++) {
        int row = r0b + rg * 8 + r;
        *(float4*)&g_e[(size_t)row * 32 + c4] = acc[r];
    }
}

// ---------------- c-GEMM: c[E,128] = e[E,32] @ Wpre_edgepart (128 rows/block) ----------------
__global__ __launch_bounds__(256) void k_cgemm(const float* __restrict__ W_pre) {
    __shared__ float sA[128 * 36];
    __shared__ float sW[32 * 128];   // [j][o], o = t*32+g
    int r0b = blockIdx.x * 128;
    int tid = threadIdx.x;
    for (int i = tid; i < 32 * 32; i += 256) {
        int j = i >> 5, og = (i & 31) * 4;
        int t = og >> 5, g = og & 31;
        *(float4*)&sW[j * 128 + og] = *(const float4*)&W_pre[t * 3072 + (64 + j) * 32 + g];
    }
    for (int i = tid; i < 128 * 8; i += 256) {
        int r = i >> 3, kg = (i & 7) * 4;
        *(float4*)&sA[r * 36 + kg] = *(const float4*)&g_e[(size_t)(r0b + r) * 32 + kg];
    }
    __syncthreads();
    int c4 = (tid & 31) * 4;
    int rg = tid >> 5;               // 8 groups of 16 rows
    float4 acc[16];
#pragma unroll
    for (int r = 0; r < 16; r++) acc[r] = make_float4(0.f, 0.f, 0.f, 0.f);
#pragma unroll
    for (int k4 = 0; k4 < 8; k4++) {
        float4 w0 = *(float4*)&sW[(k4 * 4 + 0) * 128 + c4];
        float4 w1 = *(float4*)&sW[(k4 * 4 + 1) * 128 + c4];
        float4 w2 = *(float4*)&sW[(k4 * 4 + 2) * 128 + c4];
        float4 w3 = *(float4*)&sW[(k4 * 4 + 3) * 128 + c4];
#pragma unroll
        for (int r = 0; r < 16; r++) {
            float4 a = *(float4*)&sA[(rg * 16 + r) * 36 + k4 * 4];
            acc[r].x = fmaf(a.x, w0.x, fmaf(a.y, w1.x, fmaf(a.z, w2.x, fmaf(a.w, w3.x, acc[r].x))));
            acc[r].y = fmaf(a.x, w0.y, fmaf(a.y, w1.y, fmaf(a.z, w2.y, fmaf(a.w, w3.y, acc[r].y))));
            acc[r].z = fmaf(a.x, w0.z, fmaf(a.y, w1.z, fmaf(a.z, w2.z, fmaf(a.w, w3.z, acc[r].z))));
            acc[r].w = fmaf(a.x, w0.w, fmaf(a.y, w1.w, fmaf(a.z, w2.w, fmaf(a.w, w3.w, acc[r].w))));
        }
    }
#pragma unroll
    for (int r = 0; r < 16; r++) {
        int row = r0b + rg * 16 + r;
        *(float4*)&g_c[(size_t)row * 128 + c4] = acc[r];
    }
}

// ---------------- aggregation: one warp per node (sorted edge list) ----------------
__global__ __launch_bounds__(256) void k_agg(const int* __restrict__ srcp) {
    __shared__ int s_eid[8][128];
    int w = threadIdx.x >> 5;
    int lane = threadIdx.x & 31;
    int n = blockIdx.x * 8 + w;
    if (n >= NN) return;
    int start = g_rowptr[n], end = g_rowptr[n + 1];
    int deg = end - start;
    int msort = deg < 128 ? deg : 128;

    for (int j = lane; j < msort; j += 32) s_eid[w][j] = g_eid[start + j];
    __syncwarp();
    for (int pass = 0; pass < msort; pass++) {
        int off = pass & 1;
        for (int j = lane; 2 * j + 1 + off < msort; j += 32) {
            int i0 = 2 * j + off, i1 = i0 + 1;
            int a = s_eid[w][i0], b = s_eid[w][i1];
            if (a > b) { s_eid[w][i0] = b; s_eid[w][i1] = a; }
        }
        __syncwarp();
    }

    float4 base = *(const float4*)&g_a[(size_t)n * 128 + lane * 4];
    float4 bm   = *(const float4*)&g_biasm[lane * 4];
    base.x += bm.x; base.y += bm.y; base.z += bm.z; base.w += bm.w;

    float4 s  = make_float4(0.f, 0.f, 0.f, 0.f);
    float4 sq = make_float4(0.f, 0.f, 0.f, 0.f);
    float4 mx = make_float4(-FMAXV, -FMAXV, -FMAXV, -FMAXV);
    float4 mn = make_float4( FMAXV,  FMAXV,  FMAXV,  FMAXV);

    for (int sl = 0; sl < deg; sl++) {
        int eid = (sl < 128) ? s_eid[w][sl] : __ldg(&g_eid[start + sl]);
        int sn  = __ldg(&srcp[eid]);
        float4 c = *(const float4*)&g_c[(size_t)eid * 128 + lane * 4];
        float4 b = *(const float4*)&g_b[(size_t)sn * 128 + lane * 4];
        float m0 = base.x + b.x + c.x;
        float m1 = base.y + b.y + c.y;
        float m2 = base.z + b.z + c.z;
        float m3 = base.w + b.w + c.w;
        s.x += m0; s.y += m1; s.z += m2; s.w += m3;
        sq.x = fmaf(m0, m0, sq.x); sq.y = fmaf(m1, m1, sq.y);
        sq.z = fmaf(m2, m2, sq.z); sq.w = fmaf(m3, m3, sq.w);
        mx.x = fmaxf(mx.x, m0); mx.y = fmaxf(mx.y, m1); mx.z = fmaxf(mx.z, m2); mx.w = fmaxf(mx.w, m3);
        mn.x = fminf(mn.x, m0); mn.y = fminf(mn.y, m1); mn.z = fminf(mn.z, m2); mn.w = fminf(mn.w, m3);
    }
    if (deg == 0) {
        mx = make_float4(0.f, 0.f, 0.f, 0.f);
        mn = make_float4(0.f, 0.f, 0.f, 0.f);
    }
    float cs = (float)(deg > 0 ? deg : 1);
    float inv = 1.0f / cs;
    float4 mean = make_float4(s.x * inv, s.y * inv, s.z * inv, s.w * inv);
    float4 msq  = make_float4(sq.x * inv, sq.y * inv, sq.z * inv, sq.w * inv);
    float4 sd;
    sd.x = sqrtf(fmaxf(msq.x - mean.x * mean.x, 0.f) + 1e-5f);
    sd.y = sqrtf(fmaxf(msq.y - mean.y * mean.y, 0.f) + 1e-5f);
    sd.z = sqrtf(fmaxf(msq.z - mean.z * mean.z, 0.f) + 1e-5f);
    sd.w = sqrtf(fmaxf(msq.w - mean.w * mean.w, 0.f) + 1e-5f);

    int t = (lane * 4) >> 5, g0 = (lane * 4) & 31;
    float* aggp = &g_agg[(size_t)n * 512 + t * 128 + g0];
    *(float4*)&aggp[0]  = mean;
    *(float4*)&aggp[32] = mx;
    *(float4*)&aggp[64] = mn;
    *(float4*)&aggp[96] = sd;

    if (lane == 0) {
        float avg = g_avglog;
        float logd = logf((float)deg + 1.0f);
        g_s1[n] = logd / avg;
        g_s2[n] = (deg == 0) ? 1.0f : (avg / logd);
    }
}

// ---------------- post-MLP (R2 scalar) ----------------
__global__ __launch_bounds__(256) void k_post(const float* __restrict__ x,
                                              const float* __restrict__ W_post,
                                              const float* __restrict__ b_post) {
    __shared__ float s_w0[32 * 32];
    __shared__ float s_w1[32 * 32];
    __shared__ float s_w2[32 * 32];
    __shared__ float s_w3[32 * 32];
    __shared__ float s_xt[64 * 32];
    __shared__ float s_ag[64 * 32];
    __shared__ float s_c1[64], s_c2[64];

    int t  = blockIdx.y;
    int n0 = blockIdx.x * 64;
    int tid = threadIdx.x;
    int g = tid & 31;
    int rslot = tid >> 5;
    const float* Wt = W_post + (size_t)t * 416 * 32;

    for (int i = tid; i < 32 * 32; i += 256) s_w0[i] = Wt[i];
    for (int i = tid; i < 64 * 32; i += 256) {
        int r = i >> 5, f = i & 31;
        s_xt[i] = x[(size_t)(n0 + r) * 128 + t * 32 + f];
    }
    if (tid < 64) { s_c1[tid] = g_s1[n0 + tid]; s_c2[tid] = g_s2[n0 + tid]; }
    __syncthreads();

    float acc1[8], acc2[8], acc3[8];
#pragma unroll
    for (int r = 0; r < 8; r++) { acc1[r] = 0.f; acc2[r] = 0.f; acc3[r] = 0.f; }

#pragma unroll 4
    for (int f = 0; f < 32; f++) {
        float w0 = s_w0[f * 32 + g];
#pragma unroll
        for (int r = 0; r < 8; r++)
            acc1[r] = fmaf(s_xt[(rslot * 8 + r) * 32 + f], w0, acc1[r]);
    }

    for (int kt = 0; kt < 4; kt++) {
        int k0 = kt * 32;
        __syncthreads();
        for (int i = tid; i < 32 * 32; i += 256) {
            int kk = i >> 5, gg = i & 31;
            s_w1[i] = Wt[(32 + k0 + kk) * 32 + gg];
            s_w2[i] = Wt[(160 + k0 + kk) * 32 + gg];
            s_w3[i] = Wt[(288 + k0 + kk) * 32 + gg];
        }
        for (int i = tid; i < 64 * 32; i += 256) {
            int r = i >> 5, kk = i & 31;
            s_ag[i] = g_agg[(size_t)(n0 + r) * 512 + t * 128 + k0 + kk];
        }
        __syncthreads();
#pragma unroll 4
        for (int k = 0; k < 32; k++) {
            float w1 = s_w1[k * 32 + g];
            float w2 = s_w2[k * 32 + g];
            float w3 = s_w3[k * 32 + g];
#pragma unroll
            for (int r = 0; r < 8; r++) {
                float a = s_ag[(rslot * 8 + r) * 32 + k];
                acc1[r] = fmaf(a, w1, acc1[r]);
                acc2[r] = fmaf(a, w2, acc2[r]);
                acc3[r] = fmaf(a, w3, acc3[r]);
            }
        }
    }

    float bp = b_post[t * 32 + g];
#pragma unroll
    for (int r = 0; r < 8; r++) {
        int row = rslot * 8 + r;
        float y = acc1[r] + s_c1[row] * acc2[r] + s_c2[row] * acc3[r] + bp;
        g_Z[(size_t)(n0 + row) * 128 + t * 32 + g] = y;
    }
}

// ---------------- final (R2 scalar) ----------------
__global__ __launch_bounds__(256) void k_final(const float* __restrict__ x,
                                               const float* __restrict__ b_lin,
                                               float* __restrict__ out) {
    __shared__ float sA[64 * 36];
    __shared__ float sW[32 * 128];
    int r0b = blockIdx.x * 64;
    int tid = threadIdx.x;
    int c4 = (tid & 31) * 4;
    int rg = tid >> 5;
    float4 acc[8];
#pragma unroll
    for (int r = 0; r < 8; r++) acc[r] = make_float4(0.f, 0.f, 0.f, 0.f);

    for (int k0 = 0; k0 < 128; k0 += 32) {
        __syncthreads();
        for (int i = tid; i < 64 * 8; i += 256) {
            int r = i >> 3, kg = (i & 7) * 4;
            *(float4*)&sA[r * 36 + kg] = *(const float4*)&g_Z[(size_t)(r0b + r) * 128 + k0 + kg];
        }
        for (int i = tid; i < 32 * 32; i += 256) {
            int kk = i >> 5, cg = (i & 31) * 4;
            *(float4*)&sW[kk * 128 + cg] = *(const float4*)&g_WlinT[(k0 + kk) * 128 + cg];
        }
        __syncthreads();
#pragma unroll
        for (int k4 = 0; k4 < 8; k4++) {
            float4 w0 = *(float4*)&sW[(k4 * 4 + 0) * 128 + c4];
            float4 w1 = *(float4*)&sW[(k4 * 4 + 1) * 128 + c4];
            float4 w2 = *(float4*)&sW[(k4 * 4 + 2) * 128 + c4];
            float4 w3 = *(float4*)&sW[(k4 * 4 + 3) * 128 + c4];
#pragma unroll
            for (int r = 0; r < 8; r++) {
                float4 a = *(float4*)&sA[(rg * 8 + r) * 36 + k4 * 4];
                acc[r].x = fmaf(a.x, w0.x, fmaf(a.y, w1.x, fmaf(a.z, w2.x, fmaf(a.w, w3.x, acc[r].x))));
                acc[r].y = fmaf(a.x, w0.y, fmaf(a.y, w1.y, fmaf(a.z, w2.y, fmaf(a.w, w3.y, acc[r].y))));
                acc[r].z = fmaf(a.x, w0.z, fmaf(a.y, w1.z, fmaf(a.z, w2.z, fmaf(a.w, w3.z, acc[r].z))));
                acc[r].w = fmaf(a.x, w0.w, fmaf(a.y, w1.w, fmaf(a.z, w2.w, fmaf(a.w, w3.w, acc[r].w))));
            }
        }
    }
#pragma unroll
    for (int r = 0; r < 8; r++) {
        int row = r0b + rg * 8 + r;
        float4 bl = *(const float4*)&b_lin[c4];
        float4 xr = *(const float4*)&x[(size_t)row * 128 + c4];
        acc[r].x += bl.x + xr.x;
        acc[r].y += bl.y + xr.y;
        acc[r].z += bl.z + xr.z;
        acc[r].w += bl.w + xr.w;
        *(float4*)&out[(size_t)row * 128 + c4] = acc[r];
    }
}

// ---------------- launch ----------------
extern "C" void kernel_launch(void* const* d_in, const int* in_sizes, int n_in,
                              void* d_out, int out_size) {
    const float* x         = (const float*)d_in[0];
    const float* edge_attr = (const float*)d_in[1];
    const int*   edge_idx  = (const int*)d_in[2];
    const float* W_edge    = (const float*)d_in[3];
    const float* b_edge    = (const float*)d_in[4];
    const float* W_pre     = (const float*)d_in[5];
    const float* b_pre     = (const float*)d_in[6];
    const float* W_post    = (const float*)d_in[7];
    const float* b_post    = (const float*)d_in[8];
    const float* W_lin     = (const float*)d_in[9];
    const float* b_lin     = (const float*)d_in[10];
    float* out = (float*)d_out;

    const int* srcp = edge_idx;
    const int* dstp = edge_idx + EE;

    k_zero<<<NN / 256, 256>>>();
    k_prep<<<64, 256>>>(W_edge, W_lin, W_pre, b_pre, b_edge);
    k_hist<<<EE / 256, 256>>>(dstp);
    k_scan1<<<256, 256>>>();
    k_scan2<<<1, 256>>>();
    k_scan3<<<256, 256>>>();
    k_scatter<<<EE / 256, 256>>>(dstp);
    k_ab<<<(NN * 128) / 256, 256>>>(x, W_pre);
    k_egemm<<<EE / 256, 256>>>(edge_attr);
    k_cgemm<<<EE / 128, 256>>>(W_pre);
    k_agg<<<NN / 8, 256>>>(srcp);
    k_post<<<dim3(NN / 64, 4), 256>>>(x, W_post, b_post);
    k_final<<<NN / 64, 256>>>(x, b_lin, out);
}